// round 1
// baseline (speedup 1.0000x reference)
#include <cuda_runtime.h>
#include <cuda_bf16.h>

#define BB 8192
#define SS 10
#define HH 1024
#define NTHREADS 256
#define ALPHA_ROWS 16200

// Per-row margin scratch (deterministic two-pass reduction; no allocations).
__device__ float g_row_margin[BB];

// ---------------------------------------------------------------------------
// Kernel 1: one block per batch row. Computes all 10 pairwise distances,
// derives pos (d[sense_id]) and neg (d[argmin masked]), writes per-row margin.
// ---------------------------------------------------------------------------
__global__ __launch_bounds__(NTHREADS) void row_kernel(
    const float* __restrict__ sentence,
    const float* __restrict__ all_gloss,
    const int*   __restrict__ sense_mask,
    const int*   __restrict__ sense_ids)
{
    const int row = blockIdx.x;
    const int t   = threadIdx.x;

    // Each thread owns float4 lane t of the H=1024 row (256*4 = 1024).
    const float4* s4 = (const float4*)(sentence + (size_t)row * HH);
    const float4* g4 = (const float4*)(all_gloss + (size_t)row * SS * HH);

    const float4 sv = s4[t];

    float acc[SS];
#pragma unroll
    for (int s = 0; s < SS; s++) {
        const float4 gv = g4[s * (HH / 4) + t];   // coalesced 128B/warp
        float dx = sv.x - gv.x + 1e-6f;
        float dy = sv.y - gv.y + 1e-6f;
        float dz = sv.z - gv.z + 1e-6f;
        float dw = sv.w - gv.w + 1e-6f;
        acc[s] = dx * dx + dy * dy + dz * dz + dw * dw;
    }

    // Warp tree-reduce each of the 10 partial sums.
#pragma unroll
    for (int s = 0; s < SS; s++) {
#pragma unroll
        for (int o = 16; o > 0; o >>= 1)
            acc[s] += __shfl_xor_sync(0xffffffffu, acc[s], o);
    }

    __shared__ float sh[NTHREADS / 32][SS];
    const int warp = t >> 5, lane = t & 31;
    if (lane == 0) {
#pragma unroll
        for (int s = 0; s < SS; s++) sh[warp][s] = acc[s];
    }
    __syncthreads();

    if (t == 0) {
        float d[SS];
#pragma unroll
        for (int s = 0; s < SS; s++) {
            float v = 0.0f;
#pragma unroll
            for (int w = 0; w < NTHREADS / 32; w++) v += sh[w][s];
            d[s] = sqrtf(v);
        }

        const int sid = sense_ids[row];
        const float pos = d[sid];

        // argmin over masked values; ties -> first index (strict <).
        float best = 1e30f;
        int   bi   = 0;
#pragma unroll
        for (int s = 0; s < SS; s++) {
            const bool valid = (sense_mask[row * SS + s] != 0) && (s != sid);
            const float m = valid ? d[s] : 10.0f;
            if (m < best) { best = m; bi = s; }
        }
        const float neg = d[bi];   // real distance at argmin (even if masked slot won)

        g_row_margin[row] = fmaxf(pos - neg + 0.5f, 0.0f);
    }
}

// ---------------------------------------------------------------------------
// Kernel 2: single block. Deterministically reduces per-row margins and
// computes the alpha term, then writes loss / margin / alpha_term.
// ---------------------------------------------------------------------------
__global__ __launch_bounds__(1024) void reduce_kernel(
    const float* __restrict__ alpha,
    float* __restrict__ out,
    int out_size)
{
    const int t = threadIdx.x;

    float msum = 0.0f;
    for (int i = t; i < BB; i += 1024) msum += g_row_margin[i];

    float asum = 0.0f;
    for (int r = t; r < ALPHA_ROWS; r += 1024) {
        float mx = -1e30f, rs = 0.0f;
#pragma unroll
        for (int k = 0; k < 10; k++) {
            const float v = alpha[r * 10 + k];
            rs += v;
            mx = fmaxf(mx, v);
        }
        // row_sum == 0 -> tmp = ones -> |max-1| = 0
        asum += (rs == 0.0f) ? 0.0f : fabsf(mx - 1.0f);
    }

    // Block reduction (fixed order -> deterministic).
    __shared__ float shm[32], sha[32];
#pragma unroll
    for (int o = 16; o > 0; o >>= 1) {
        msum += __shfl_xor_sync(0xffffffffu, msum, o);
        asum += __shfl_xor_sync(0xffffffffu, asum, o);
    }
    const int warp = t >> 5, lane = t & 31;
    if (lane == 0) { shm[warp] = msum; sha[warp] = asum; }
    __syncthreads();
    if (warp == 0) {
        msum = shm[lane];
        asum = sha[lane];
#pragma unroll
        for (int o = 16; o > 0; o >>= 1) {
            msum += __shfl_xor_sync(0xffffffffu, msum, o);
            asum += __shfl_xor_sync(0xffffffffu, asum, o);
        }
        if (t == 0) {
            const float loss = msum * 0.875f + asum * 0.125f;
            out[0] = loss;
            if (out_size >= 2) out[1] = msum;
            if (out_size >= 3) out[2] = asum;
        }
    }
}

extern "C" void kernel_launch(void* const* d_in, const int* in_sizes, int n_in,
                              void* d_out, int out_size) {
    // Identify inputs by element count (all distinct):
    //   sentence 8388608, all_gloss 83886080, alpha 162000, sense_mask 81920, sense_ids 8192
    const float* sentence   = nullptr;
    const float* all_gloss  = nullptr;
    const float* alpha      = nullptr;
    const int*   sense_mask = nullptr;
    const int*   sense_ids  = nullptr;

    for (int i = 0; i < n_in; i++) {
        switch (in_sizes[i]) {
            case BB * HH:        sentence   = (const float*)d_in[i]; break;
            case BB * SS * HH:   all_gloss  = (const float*)d_in[i]; break;
            case 2700 * 6 * 10:  alpha      = (const float*)d_in[i]; break;
            case BB * SS:        sense_mask = (const int*)d_in[i];   break;
            case BB:             sense_ids  = (const int*)d_in[i];   break;
            default: break;
        }
    }

    row_kernel<<<BB, NTHREADS>>>(sentence, all_gloss, sense_mask, sense_ids);
    reduce_kernel<<<1, 1024>>>(alpha, (float*)d_out, out_size);
}

// round 2
// speedup vs baseline: 1.1332x; 1.1332x over previous
#include <cuda_runtime.h>
#include <cuda_bf16.h>

#define BB 8192
#define SS 10
#define HH 1024
#define NTHREADS 256
#define ALPHA_ROWS 16200

// Scratch (deterministic two-pass reduction; no allocations).
__device__ float g_row_margin[BB];
__device__ float g_alpha_partial[BB];

// ---------------------------------------------------------------------------
// Kernel 1: one block per batch row.
//  - Computes all 10 pairwise distances, derives pos (d[sense_id]) and
//    neg (d[argmin masked]), writes per-row margin.
//  - Additionally, block b processes alpha rows {2b, 2b+1} (two threads in
//    different warps), writing one alpha partial per block. This work is
//    fully hidden behind the DRAM-bound gloss streaming.
// ---------------------------------------------------------------------------
__global__ __launch_bounds__(NTHREADS) void row_kernel(
    const float* __restrict__ sentence,
    const float* __restrict__ all_gloss,
    const int*   __restrict__ sense_mask,
    const int*   __restrict__ sense_ids,
    const float* __restrict__ alpha)
{
    const int row = blockIdx.x;
    const int t   = threadIdx.x;

    // ---- alpha side-work: threads 32 and 96 each handle one alpha row ----
    __shared__ float sh_alpha[2];
    if (t == 32 || t == 96) {
        const int slot = (t == 32) ? 0 : 1;
        const int r = row * 2 + slot;
        float contrib = 0.0f;
        if (r < ALPHA_ROWS) {
            float mx = -1e30f, rs = 0.0f;
#pragma unroll
            for (int k = 0; k < 10; k++) {
                const float v = alpha[r * 10 + k];
                rs += v;
                mx = fmaxf(mx, v);
            }
            // row_sum == 0 -> tmp = ones -> |max-1| = 0
            contrib = (rs == 0.0f) ? 0.0f : fabsf(mx - 1.0f);
        }
        sh_alpha[slot] = contrib;
    }

    // ---- main distance streaming ----
    // Each thread owns float4 lane t of the H=1024 row (256*4 = 1024).
    const float4* s4 = (const float4*)(sentence + (size_t)row * HH);
    const float4* g4 = (const float4*)(all_gloss + (size_t)row * SS * HH);

    const float4 sv = s4[t];

    float acc[SS];
#pragma unroll
    for (int s = 0; s < SS; s++) {
        const float4 gv = g4[s * (HH / 4) + t];   // coalesced 128B/warp
        float dx = sv.x - gv.x + 1e-6f;
        float dy = sv.y - gv.y + 1e-6f;
        float dz = sv.z - gv.z + 1e-6f;
        float dw = sv.w - gv.w + 1e-6f;
        acc[s] = dx * dx + dy * dy + dz * dz + dw * dw;
    }

    // Warp tree-reduce each of the 10 partial sums.
#pragma unroll
    for (int s = 0; s < SS; s++) {
#pragma unroll
        for (int o = 16; o > 0; o >>= 1)
            acc[s] += __shfl_xor_sync(0xffffffffu, acc[s], o);
    }

    __shared__ float sh[NTHREADS / 32][SS];
    const int warp = t >> 5, lane = t & 31;
    if (lane == 0) {
#pragma unroll
        for (int s = 0; s < SS; s++) sh[warp][s] = acc[s];
    }
    __syncthreads();

    if (t == 0) {
        float d[SS];
#pragma unroll
        for (int s = 0; s < SS; s++) {
            float v = 0.0f;
#pragma unroll
            for (int w = 0; w < NTHREADS / 32; w++) v += sh[w][s];
            d[s] = sqrtf(v);
        }

        const int sid = sense_ids[row];
        const float pos = d[sid];

        // argmin over masked values; ties -> first index (strict <).
        float best = 1e30f;
        int   bi   = 0;
#pragma unroll
        for (int s = 0; s < SS; s++) {
            const bool valid = (sense_mask[row * SS + s] != 0) && (s != sid);
            const float m = valid ? d[s] : 10.0f;
            if (m < best) { best = m; bi = s; }
        }
        const float neg = d[bi];   // real distance at argmin (even if masked slot won)

        g_row_margin[row]    = fmaxf(pos - neg + 0.5f, 0.0f);
        g_alpha_partial[row] = sh_alpha[0] + sh_alpha[1];
    }
}

// ---------------------------------------------------------------------------
// Kernel 2: single block, 1024 threads. Reads 8192 margins + 8192 alpha
// partials (64 KB, L2-resident) with float4 loads. Deterministic order.
// ---------------------------------------------------------------------------
__global__ __launch_bounds__(1024) void final_kernel(
    float* __restrict__ out,
    int out_size)
{
    const int t = threadIdx.x;

    const float4* m4 = (const float4*)g_row_margin;
    const float4* a4 = (const float4*)g_alpha_partial;

    float msum = 0.0f, asum = 0.0f;
#pragma unroll
    for (int i = 0; i < 2; i++) {
        const float4 mv = m4[t + i * 1024];
        const float4 av = a4[t + i * 1024];
        msum += (mv.x + mv.y) + (mv.z + mv.w);
        asum += (av.x + av.y) + (av.z + av.w);
    }

    // Block reduction (fixed order -> deterministic).
    __shared__ float shm[32], sha[32];
#pragma unroll
    for (int o = 16; o > 0; o >>= 1) {
        msum += __shfl_xor_sync(0xffffffffu, msum, o);
        asum += __shfl_xor_sync(0xffffffffu, asum, o);
    }
    const int warp = t >> 5, lane = t & 31;
    if (lane == 0) { shm[warp] = msum; sha[warp] = asum; }
    __syncthreads();
    if (warp == 0) {
        msum = shm[lane];
        asum = sha[lane];
#pragma unroll
        for (int o = 16; o > 0; o >>= 1) {
            msum += __shfl_xor_sync(0xffffffffu, msum, o);
            asum += __shfl_xor_sync(0xffffffffu, asum, o);
        }
        if (t == 0) {
            const float loss = msum * 0.875f + asum * 0.125f;
            out[0] = loss;
            if (out_size >= 2) out[1] = msum;
            if (out_size >= 3) out[2] = asum;
        }
    }
}

extern "C" void kernel_launch(void* const* d_in, const int* in_sizes, int n_in,
                              void* d_out, int out_size) {
    // Identify inputs by element count (all distinct):
    //   sentence 8388608, all_gloss 83886080, alpha 162000, sense_mask 81920, sense_ids 8192
    const float* sentence   = nullptr;
    const float* all_gloss  = nullptr;
    const float* alpha      = nullptr;
    const int*   sense_mask = nullptr;
    const int*   sense_ids  = nullptr;

    for (int i = 0; i < n_in; i++) {
        switch (in_sizes[i]) {
            case BB * HH:        sentence   = (const float*)d_in[i]; break;
            case BB * SS * HH:   all_gloss  = (const float*)d_in[i]; break;
            case 2700 * 6 * 10:  alpha      = (const float*)d_in[i]; break;
            case BB * SS:        sense_mask = (const int*)d_in[i];   break;
            case BB:             sense_ids  = (const int*)d_in[i];   break;
            default: break;
        }
    }

    row_kernel<<<BB, NTHREADS>>>(sentence, all_gloss, sense_mask, sense_ids, alpha);
    final_kernel<<<1, 1024>>>((float*)d_out, out_size);
}